// round 8
// baseline (speedup 1.0000x reference)
#include <cuda_runtime.h>
#include <math.h>

#define Bn 256
#define Tn 100
#define Fn 256
#define Hn 512
#define NB 128
#define NT 512
#define BT (Bn * Tn)
#define STW 8192                   // stage words: A 4096 + B 4096
#define NSTG 4
#define EPIT 68
#define SMEM_WORDS (NSTG * STW + 512)
#define SMEM_BYTES (SMEM_WORDS * 4)
#define BTF ((size_t)Bn * Tn * Fn)

// ---------------- global scratch (allocation-free rule) ----------------
__device__ unsigned g_dtq[(size_t)400 * 4 * 4096];   // deltas quads, bt-tiles
__device__ unsigned g_gxmq[(size_t)400 * 8 * 4096];  // [gamma_x | mask] quads
__device__ unsigned g_mq[(size_t)4 * Tn * 4 * 4096]; // masks quads, (group,t)-tiles
__device__ unsigned g_Wtdhq[8 * 4 * 4096];
__device__ unsigned g_Wcombq[4 * 8 * 4096];
__device__ unsigned g_Whistq[8 * 8 * 2048];
__device__ unsigned g_Wfeatq[8 * 4 * 2048];
__device__ unsigned g_Wgq[32 * 16 * 4096];           // gates W, rows j*4+gate
__device__ unsigned g_hq[2 * 4 * 8 * 4096];          // h_dec quads (double buffer)
__device__ unsigned g_xcq[4 * 4 * 4096];
__device__ unsigned g_ccq[4 * 4 * 4096];
__device__ float g_gamma_h[(size_t)BT * Hn];
__device__ float g_alpha[(size_t)BT * Fn];
__device__ float g_bg[4 * Hn];
__device__ float g_cst[Bn * Hn];
__device__ float g_l1[Tn * 32], g_l2[Tn * 32], g_l3[Tn * 32], g_den[Tn * 32];
__device__ unsigned g_cnt, g_sense;
__device__ unsigned g_cnt_h[4], g_cnt_xh[4], g_cnt_cc[4];

__device__ __forceinline__ float sigmoidf_(float x) { return 1.0f / (1.0f + expf(-x)); }

__device__ __forceinline__ unsigned f2tf(float f) {
    unsigned u;
    asm("cvt.rna.tf32.f32 %0, %1;" : "=r"(u) : "f"(f));
    return u;
}

// quad layouts (same as round 7)
__device__ __forceinline__ int o_A(int r, int k) {
    return ((r >> 4) * 8 + (k >> 3)) * 128 + ((r & 7) * 4 + (k & 3)) * 4 +
           ((k & 4) >> 1) + ((r & 8) >> 3);
}
__device__ __forceinline__ int o_B(int n, int k) {
    return ((n >> 4) * 8 + (k >> 3)) * 128 + ((n & 7) * 4 + (k & 3)) * 4 +
           ((n >> 3) & 1) * 2 + ((k >> 2) & 1);
}

#define MMA(d, A0, A1, A2, A3, B0, B1)                                          \
    asm volatile("mma.sync.aligned.m16n8k8.row.col.f32.tf32.tf32.f32 "          \
                 "{%0,%1,%2,%3},{%4,%5,%6,%7},{%8,%9},{%0,%1,%2,%3};"           \
                 : "+f"(d[0]), "+f"(d[1]), "+f"(d[2]), "+f"(d[3])               \
                 : "r"(A0), "r"(A1), "r"(A2), "r"(A3), "r"(B0), "r"(B1))

#define CPA(boff, p)                                                            \
    asm volatile("cp.async.cg.shared.global [%0], [%1], 16;"                    \
                 :: "r"(sbase + (unsigned)(boff)), "l"(p) : "memory")
#define CMT   asm volatile("cp.async.commit_group;" ::: "memory")
#define WAIT2 asm volatile("cp.async.wait_group 2;" ::: "memory")

// 64x64 stage: A 4096 + B 4096 words, linear copy (512 thr -> 4 CP16 each)
#define LOADQ64(pA, pB, s) do {                                                 \
    unsigned _off = (unsigned)((s) * STW * 4);                                  \
    _Pragma("unroll")                                                           \
    for (int _j = 0; _j < 2; _j++) { int _c = tid + _j * 512;                   \
        CPA(_off + (unsigned)_c * 16u, (pA) + _c * 4);                          \
        CPA(_off + 16384u + (unsigned)_c * 16u, (pB) + _c * 4); }               \
} while (0)
// 64x32 stage: A 4096 + B 2048 words
#define LOADQ32(pA, pB, s) do {                                                 \
    unsigned _off = (unsigned)((s) * STW * 4);                                  \
    _Pragma("unroll")                                                           \
    for (int _j = 0; _j < 2; _j++) { int _c = tid + _j * 512;                   \
        CPA(_off + (unsigned)_c * 16u, (pA) + _c * 4); }                        \
    { int _c = tid;                                                             \
        CPA(_off + 16384u + (unsigned)_c * 16u, (pB) + _c * 4); }               \
} while (0)

// ---------------- sync primitives (proven) ----------------
__device__ __forceinline__ void gsync(unsigned& sense) {
    __threadfence();
    __syncthreads();
    unsigned target = sense ^ 1u;
    if (threadIdx.x == 0) {
        unsigned old = atomicAdd(&g_cnt, 1u);
        if (old == NB - 1) {
            g_cnt = 0;
            __threadfence();
            atomicExch(&g_sense, target);
        } else {
            while (atomicAdd(&g_sense, 0u) != target) { __nanosleep(128); }
        }
        __threadfence();
    }
    sense = target;
    __syncthreads();
}
__device__ __forceinline__ void wait_ge(unsigned* cnt, unsigned target) {
    if (threadIdx.x == 0) {
        while (atomicAdd(cnt, 0u) < target) { __nanosleep(64); }
        __threadfence();
    }
    __syncthreads();
}
__device__ __forceinline__ void arrive(unsigned* cnt) {
    __threadfence();
    __syncthreads();
    if (threadIdx.x == 0) atomicAdd(cnt, 1u);
}
__device__ __forceinline__ float wredsum(float v) {
#pragma unroll
    for (int o = 16; o; o >>= 1) v += __shfl_xor_sync(0xffffffffu, v, o);
    return v;
}

// ---------------- quad MMA bodies (16 warps) ----------------
// 64x64 tile: warps 4(M)x4(N), warp tile 16x16
__device__ __forceinline__ void mma64q(const unsigned* As, const unsigned* Bs,
                                       float acc[2][4], int wm, int wn, int lane) {
#pragma unroll
    for (int ks = 0; ks < 8; ks++) {
        uint4 a = *(const uint4*)&As[((wm * 8 + ks) * 32 + lane) * 4];
        uint4 b = *(const uint4*)&Bs[((wn * 8 + ks) * 32 + lane) * 4];
        MMA(acc[0], a.x, a.y, a.z, a.w, b.x, b.y);
        MMA(acc[1], a.x, a.y, a.z, a.w, b.z, b.w);
    }
}
// 64x32 tile: warps 4(M)x4(N), warp tile 16x8 (two warps share a B block)
__device__ __forceinline__ void mma32q(const unsigned* As, const unsigned* Bs,
                                       float acc[4], int wm, int wn, int lane) {
    const int nt = wn >> 1, hi = wn & 1;
#pragma unroll
    for (int ks = 0; ks < 8; ks++) {
        uint4 a = *(const uint4*)&As[((wm * 8 + ks) * 32 + lane) * 4];
        uint4 b = *(const uint4*)&Bs[((nt * 8 + ks) * 32 + lane) * 4];
        unsigned b0 = hi ? b.z : b.x;
        unsigned b1 = hi ? b.w : b.y;
        MMA(acc, a.x, a.y, a.z, a.w, b0, b1);
    }
}

__device__ __forceinline__ const unsigned* pcA(int g, int t, int par, int kc) {
    if (kc < 4)  return g_ccq + ((size_t)g * 4 + kc) * 4096;
    if (kc < 8)  return g_mq + (((size_t)g * Tn + t) * 4 + (kc - 4)) * 4096;
    return g_hq + (((size_t)par * 4 + g) * 8 + (kc - 8)) * 4096;
}

__global__ void __launch_bounds__(NT, 1) rits_kernel(
    const float* __restrict__ values, const float* __restrict__ masks,
    const float* __restrict__ deltas,
    const float* __restrict__ W_td_h, const float* __restrict__ b_td_h,
    const float* __restrict__ W_td_x, const float* __restrict__ b_td_x,
    const float* __restrict__ W_hist, const float* __restrict__ b_hist,
    const float* __restrict__ W_feat, const float* __restrict__ b_feat,
    const float* __restrict__ W_comb, const float* __restrict__ b_comb,
    const float* __restrict__ W_ih, const float* __restrict__ W_hh,
    const float* __restrict__ b_ih, const float* __restrict__ b_hh,
    float* __restrict__ out)
{
    extern __shared__ unsigned SHu[];
    float* RED = (float*)(SHu + NSTG * STW);
    unsigned sbase = (unsigned)__cvta_generic_to_shared(SHu);

    const int tid = threadIdx.x;
    const int cta = blockIdx.x;
    const int wid = tid >> 5;
    const int lane = tid & 31;
    const int gid = lane >> 2;
    const int tg = lane & 3;
    const int wm = wid & 3, wn = wid >> 2;   // 4x4 warp grid

    const int g = cta >> 5;
    const int cg = cta & 31;
    const int b0 = g * 64;

    unsigned sense = *((volatile unsigned*)&g_sense);

    // =================== init: state + tf32 quad pre-conversion ===================
    for (int i = cta * NT + tid; i < Bn * Hn; i += NB * NT) g_cst[i] = 0.0f;
    for (int i = cta * NT + tid; i < 2 * 4 * 8 * 4096; i += NB * NT) g_hq[i] = 0u;

    for (int i4 = cta * NT + tid; i4 < BT * Fn / 4; i4 += NB * NT) {
        int bt = i4 >> 6;
        int f0 = (i4 & 63) * 4;
        float4 d = ((const float4*)deltas)[i4];
        float4 mk = ((const float4*)masks)[i4];
        int u = bt >> 6, r = bt & 63;
        int b = bt / Tn;
        int tt2 = bt - b * Tn;
        int g2 = b >> 6, r2 = b & 63;
        float dv[4] = {d.x, d.y, d.z, d.w};
        float mv[4] = {mk.x, mk.y, mk.z, mk.w};
#pragma unroll
        for (int q = 0; q < 4; q++) {
            int f = f0 + q;
            int kc = f >> 6, k = f & 63;
            int oa = o_A(r, k);
            float gx = expf(-fmaxf(fmaf(dv[q], W_td_x[f * Fn + f], b_td_x[f]), 0.f));
            unsigned mu = f2tf(mv[q]);
            g_dtq[((size_t)u * 4 + kc) * 4096 + oa] = f2tf(dv[q]);
            g_gxmq[((size_t)u * 8 + kc) * 4096 + oa] = f2tf(gx);
            g_gxmq[((size_t)u * 8 + 4 + kc) * 4096 + oa] = mu;
            g_mq[(((size_t)g2 * Tn + tt2) * 4 + kc) * 4096 + o_A(r2, k)] = mu;
        }
    }
    for (int i = cta * NT + tid; i < 512 * 256; i += NB * NT) {
        int n = i >> 8, k = i & 255;
        g_Wtdhq[((n >> 6) * 4 + (k >> 6)) * 4096 + o_B(n & 63, k & 63)] = f2tf(W_td_h[i]);
    }
    for (int i = cta * NT + tid; i < 256 * 512; i += NB * NT) {
        int n = i >> 9, k = i & 511;
        g_Wcombq[((n >> 6) * 8 + (k >> 6)) * 4096 + o_B(n & 63, k & 63)] = f2tf(W_comb[i]);
        g_Whistq[((n >> 5) * 8 + (k >> 6)) * 2048 + o_B(n & 31, k & 63)] = f2tf(W_hist[i]);
    }
    for (int i = cta * NT + tid; i < 256 * 256; i += NB * NT) {
        int n = i >> 8, k = i & 255;
        float w = (n == k) ? 0.0f : W_feat[i];
        g_Wfeatq[((n >> 5) * 4 + (k >> 6)) * 2048 + o_B(n & 31, k & 63)] = f2tf(w);
    }
    for (int i = cta * NT + tid; i < 2048 * 1024; i += NB * NT) {
        int np = i >> 10, k = i & 1023;
        int j = np >> 2, gate = np & 3;
        float w = (k < 512) ? W_ih[(size_t)(gate * Hn + j) * 512 + k]
                            : W_hh[(size_t)(gate * Hn + j) * 512 + (k - 512)];
        g_Wgq[((np >> 6) * 16 + (k >> 6)) * 4096 + o_B(np & 63, k & 63)] = f2tf(w);
    }
    for (int i = cta * NT + tid; i < 4 * Hn; i += NB * NT) {
        int j = i >> 2, gate = i & 3;
        g_bg[i] = b_ih[gate * Hn + j] + b_hh[gate * Hn + j];
    }
    gsync(sense);

    // =================== precompute gamma_h (3200 tiles) + alpha (1600) ===================
    for (int tt = cta; tt < 4800; tt += NB) {
        float acc[2][4];
#pragma unroll
        for (int nf = 0; nf < 2; nf++)
#pragma unroll
            for (int e = 0; e < 4; e++) acc[nf][e] = 0.0f;

        const bool isg = (tt < 3200);
        const int u = isg ? tt : tt - 3200;
        const int ut = isg ? (u >> 3) : (u >> 2);
        const int nt = isg ? (u & 7) : (u & 3);
        const int m0 = ut * 64, n0 = nt * 64;
        const int NI = isg ? 4 : 8;
        const unsigned* Asrc = isg ? (g_dtq + (size_t)ut * 4 * 4096)
                                   : (g_gxmq + (size_t)ut * 8 * 4096);
        const unsigned* Bsrc = isg ? (g_Wtdhq + (size_t)nt * 4 * 4096)
                                   : (g_Wcombq + (size_t)nt * 8 * 4096);

        LOADQ64(Asrc, Bsrc, 0); CMT;
        LOADQ64(Asrc + 4096, Bsrc + 4096, 1); CMT;
        LOADQ64(Asrc + 8192, Bsrc + 8192, 2); CMT;
        for (int i = 0; i < NI; i++) {
            WAIT2;
            __syncthreads();
            if (i + 3 < NI)
                LOADQ64(Asrc + (size_t)(i + 3) * 4096, Bsrc + (size_t)(i + 3) * 4096, (i + 3) & 3);
            CMT;
            int s = i & 3;
            mma64q(SHu + s * STW, SHu + s * STW + 4096, acc, wm, wn, lane);
        }
        __syncthreads();
#pragma unroll
        for (int nf = 0; nf < 2; nf++) {
#pragma unroll
            for (int e = 0; e < 4; e++) {
                int bt = m0 + wm * 16 + gid + ((e >> 1) << 3);
                int n = n0 + wn * 16 + nf * 8 + 2 * tg + (e & 1);
                float v = acc[nf][e];
                if (isg)
                    g_gamma_h[(size_t)bt * Hn + n] = expf(-fmaxf(v + b_td_h[n], 0.f));
                else
                    g_alpha[(size_t)bt * Fn + n] = sigmoidf_(v + b_comb[n]);
            }
        }
    }
    gsync(sense);

    // =================== sequential recurrence (dataflow-synced, 4 groups) ===================
    for (int t = 0; t < Tn; t++) {
        const int par = t & 1, nxt = (t + 1) & 1;
        float xh_r[4], x_r[4], m_r[4];

        // ===== P_a: x_h = h_dec @ W_hist^T  (tile 64x32, K=512), CTAs cg<8 =====
        if (cg < 8) {
            const int n0 = cg * 32;
            wait_ge(&g_cnt_h[g], 32u * (unsigned)t);
            const unsigned* Ah = g_hq + (((size_t)par * 4 + g) * 8) * 4096;
            const unsigned* Bw = g_Whistq + (size_t)cg * 8 * 2048;
            float acc[4] = {0.f, 0.f, 0.f, 0.f};
            LOADQ32(Ah, Bw, 0); CMT;
            LOADQ32(Ah + 4096, Bw + 2048, 1); CMT;
            LOADQ32(Ah + 8192, Bw + 4096, 2); CMT;
            for (int i = 0; i < 8; i++) {
                WAIT2;
                __syncthreads();
                if (i + 3 < 8)
                    LOADQ32(Ah + (size_t)(i + 3) * 4096, Bw + (size_t)(i + 3) * 2048, (i + 3) & 3);
                CMT;
                int s = i & 3;
                mma32q(SHu + s * STW, SHu + s * STW + 4096, acc, wm, wn, lane);
            }
            float ls = 0.0f;
#pragma unroll
            for (int e = 0; e < 4; e++) {
                int r = wm * 16 + gid + ((e >> 1) << 3);
                int b = b0 + r;
                int f = n0 + wn * 8 + 2 * tg + (e & 1);
                float xh = acc[e] + b_hist[f];
                size_t vi = ((size_t)b * Tn + t) * Fn + f;
                float x = values[vi], m = masks[vi];
                xh_r[e] = xh; x_r[e] = x; m_r[e] = m;
                ls += fabsf(xh - x) * m;
                g_xcq[((size_t)g * 4 + (f >> 6)) * 4096 + o_A(r, f & 63)] =
                    f2tf(m * x + (1.0f - m) * xh);
            }
            ls = wredsum(ls);
            if (lane == 0) RED[wid] = ls;
            __syncthreads();
            if (tid == 0) {
                float s = 0.f;
#pragma unroll
                for (int w = 0; w < 16; w++) s += RED[w];
                g_l1[t * 32 + g * 8 + cg] = s;
            }
            arrive(&g_cnt_xh[g]);
        }

        // ===== P_b: z_h = relu(x_c @ Wf^T) (tile 64x32, K=256) + epilogue =====
        if (cg < 8) {
            const int n0 = cg * 32;
            wait_ge(&g_cnt_xh[g], 8u * (unsigned)(t + 1));
            const unsigned* Ax = g_xcq + (size_t)g * 4 * 4096;
            const unsigned* Bf = g_Wfeatq + (size_t)cg * 4 * 2048;
            float acc[4] = {0.f, 0.f, 0.f, 0.f};
            LOADQ32(Ax, Bf, 0); CMT;
            LOADQ32(Ax + 4096, Bf + 2048, 1); CMT;
            LOADQ32(Ax + 8192, Bf + 4096, 2); CMT;
            for (int i = 0; i < 4; i++) {
                WAIT2;
                __syncthreads();
                if (i + 3 < 4)
                    LOADQ32(Ax + (size_t)(i + 3) * 4096, Bf + (size_t)(i + 3) * 2048, (i + 3) & 3);
                CMT;
                int s = i & 3;
                mma32q(SHu + s * STW, SHu + s * STW + 4096, acc, wm, wn, lane);
            }
            float l2s = 0.f, l3s = 0.f, dns = 0.f;
#pragma unroll
            for (int e = 0; e < 4; e++) {
                int r = wm * 16 + gid + ((e >> 1) << 3);
                int b = b0 + r;
                int f = n0 + wn * 8 + 2 * tg + (e & 1);
                size_t vi = ((size_t)b * Tn + t) * Fn + f;
                float z = fmaxf(acc[e] + b_feat[f], 0.0f);
                float al = g_alpha[vi];
                float x = x_r[e], m = m_r[e];
                float ch = al * z + (1.0f - al) * xh_r[e];
                float cc = m * x + (1.0f - m) * ch;
                out[vi] = cc;
                g_ccq[((size_t)g * 4 + (f >> 6)) * 4096 + o_A(r, f & 63)] = f2tf(cc);
                l2s += fabsf(z - x) * m;
                l3s += fabsf(ch - x) * m;
                dns += m;
            }
            l2s = wredsum(l2s); l3s = wredsum(l3s); dns = wredsum(dns);
            if (lane == 0) { RED[wid] = l2s; RED[16 + wid] = l3s; RED[32 + wid] = dns; }
            __syncthreads();
            if (tid == 0) {
                float s2 = 0.f, s3 = 0.f, sd = 0.f;
#pragma unroll
                for (int w = 0; w < 16; w++) { s2 += RED[w]; s3 += RED[16 + w]; sd += RED[32 + w]; }
                int slot = t * 32 + g * 8 + cg;
                g_l2[slot] = s2; g_l3[slot] = s3; g_den[slot] = sd;
            }
            arrive(&g_cnt_cc[g]);
        }

        // ===== P_c: gates (tile 64x64 virt, K=1024) + fused LSTM, all 32 CTAs =====
        {
            wait_ge(&g_cnt_cc[g], 8u * (unsigned)(t + 1));
            const unsigned* Bb = g_Wgq + (size_t)cg * 16 * 4096;
            float acc[2][4];
#pragma unroll
            for (int nf = 0; nf < 2; nf++)
#pragma unroll
                for (int e = 0; e < 4; e++) acc[nf][e] = 0.0f;
            LOADQ64(pcA(g, t, par, 0), Bb, 0); CMT;
            LOADQ64(pcA(g, t, par, 1), Bb + 4096, 1); CMT;
            LOADQ64(pcA(g, t, par, 2), Bb + 8192, 2); CMT;
            for (int i = 0; i < 16; i++) {
                WAIT2;
                __syncthreads();
                if (i + 3 < 16)
                    LOADQ64(pcA(g, t, par, i + 3), Bb + (size_t)(i + 3) * 4096, (i + 3) & 3);
                CMT;
                int s = i & 3;
                mma64q(SHu + s * STW, SHu + s * STW + 4096, acc, wm, wn, lane);
            }
            __syncthreads();
            float* EP = (float*)SHu;
#pragma unroll
            for (int nf = 0; nf < 2; nf++)
#pragma unroll
                for (int e = 0; e < 4; e++) {
                    int r = wm * 16 + gid + ((e >> 1) << 3);
                    int cL = wn * 16 + nf * 8 + 2 * tg + (e & 1);
                    EP[r * EPIT + cL] = acc[nf][e];
                }
            __syncthreads();
#pragma unroll
            for (int q = 0; q < 2; q++) {
                int idx = tid + q * 512;
                int r = idx >> 4, jl = idx & 15;
                int b = b0 + r;
                int j = cg * 16 + jl;
                float ia = EP[r * EPIT + jl * 4 + 0] + g_bg[j * 4 + 0];
                float fa = EP[r * EPIT + jl * 4 + 1] + g_bg[j * 4 + 1];
                float ga = EP[r * EPIT + jl * 4 + 2] + g_bg[j * 4 + 2];
                float oa = EP[r * EPIT + jl * 4 + 3] + g_bg[j * 4 + 3];
                int ci = b * Hn + j;
                float cn = sigmoidf_(fa) * g_cst[ci] + sigmoidf_(ia) * tanhf(ga);
                float hn = sigmoidf_(oa) * tanhf(cn);
                g_cst[ci] = cn;
                if (t + 1 < Tn) {
                    float hd = hn * g_gamma_h[((size_t)b * Tn + t + 1) * Hn + j];
                    g_hq[(((size_t)nxt * 4 + g) * 8 + (j >> 6)) * 4096 + o_A(r, j & 63)] = f2tf(hd);
                } else {
                    out[BTF + ci] = hn;
                }
            }
            arrive(&g_cnt_h[g]);
        }
    }

    gsync(sense);

    // =================== final deterministic loss reduction + counter reset ===================
    if (cta == 0) {
        float v = 0.0f;
        if (tid < Tn) {
            float den = 1e-9f, n1 = 0.f, n2 = 0.f, n3 = 0.f;
            for (int c2 = 0; c2 < 32; c2++) {
                den += g_den[tid * 32 + c2];
                n1 += g_l1[tid * 32 + c2];
                n2 += g_l2[tid * 32 + c2];
                n3 += g_l3[tid * 32 + c2];
            }
            v = (n1 + n2 + n3) / den;
        }
        __syncthreads();
        RED[tid] = v;
        __syncthreads();
#pragma unroll
        for (int s = 256; s > 0; s >>= 1) {
            if (tid < s) RED[tid] += RED[tid + s];
            __syncthreads();
        }
        if (tid == 0) {
            out[BTF + Bn * Hn] = RED[0] / (3.0f * Tn);
#pragma unroll
            for (int i = 0; i < 4; i++) { g_cnt_h[i] = 0u; g_cnt_xh[i] = 0u; g_cnt_cc[i] = 0u; }
            __threadfence();
        }
    }
}

extern "C" void kernel_launch(void* const* d_in, const int* in_sizes, int n_in,
                              void* d_out, int out_size) {
    (void)in_sizes; (void)n_in; (void)out_size;
    static int configured = 0;
    if (!configured) {
        cudaFuncSetAttribute(rits_kernel, cudaFuncAttributeMaxDynamicSharedMemorySize,
                             SMEM_BYTES);
        configured = 1;
    }
    rits_kernel<<<NB, NT, SMEM_BYTES>>>(
        (const float*)d_in[0],  (const float*)d_in[1],  (const float*)d_in[2],
        (const float*)d_in[3],  (const float*)d_in[4],  (const float*)d_in[5],
        (const float*)d_in[6],  (const float*)d_in[7],  (const float*)d_in[8],
        (const float*)d_in[9],  (const float*)d_in[10], (const float*)d_in[11],
        (const float*)d_in[12], (const float*)d_in[13], (const float*)d_in[14],
        (const float*)d_in[15], (const float*)d_in[16],
        (float*)d_out);
}